// round 1
// baseline (speedup 1.0000x reference)
#include <cuda_runtime.h>

// hybrid_position_embedding: the reference ends with
//   hmap = hybrid[:, None, :]            # (B, 1, N) -- singleton axis
//   out  = softmax(hmap, axis=1)         # softmax over ONE element == 1.0
// hybrid passes through .astype(int32), so it is always a finite float32;
// exp(x - max(x)) = exp(0) = 1 exactly. Output is identically 1.0f for all
// B*N = 64*4096 = 262144 elements, independent of the input tensor.
//
// Fastest correct kernel: vectorized constant fill of d_out.

__global__ void fill_ones_kernel(float4* __restrict__ out, int n_vec4) {
    int i = blockIdx.x * blockDim.x + threadIdx.x;
    if (i < n_vec4) {
        out[i] = make_float4(1.0f, 1.0f, 1.0f, 1.0f);
    }
}

__global__ void fill_ones_tail_kernel(float* __restrict__ out, int start, int n) {
    int i = start + blockIdx.x * blockDim.x + threadIdx.x;
    if (i < n) {
        out[i] = 1.0f;
    }
}

extern "C" void kernel_launch(void* const* d_in, const int* in_sizes, int n_in,
                              void* d_out, int out_size) {
    (void)d_in; (void)in_sizes; (void)n_in;

    float* out = (float*)d_out;

    int n_vec4 = out_size >> 2;           // 262144 / 4 = 65536 float4 stores
    int tail_start = n_vec4 << 2;
    int tail = out_size - tail_start;     // 0 for this shape, handled anyway

    if (n_vec4 > 0) {
        const int threads = 256;
        int blocks = (n_vec4 + threads - 1) / threads;
        fill_ones_kernel<<<blocks, threads>>>((float4*)out, n_vec4);
    }
    if (tail > 0) {
        const int threads = 128;
        int blocks = (tail + threads - 1) / threads;
        fill_ones_tail_kernel<<<blocks, threads>>>(out, tail_start, out_size);
    }
}